// round 2
// baseline (speedup 1.0000x reference)
#include <cuda_runtime.h>

#define B_ 2048
#define N_ 64
#define D_ 256
#define MT 128
#define KT 16
#define NTHREADS 512
#define STEPS 4

// Scratch (allocation-free rule: __device__ globals)
__device__ float g_wT[(size_t)N_ * D_ * D_];   // masked, transposed: wT[n][i][j]
__device__ float g_bias[N_ * D_];              // masked bias
__device__ int   g_nact[N_];                   // active size per group

// ---------------------------------------------------------------------------
// Prep A: wT[n][i][j] = w[n][j][i] * wmask[n][j][i]  (smem-tiled transpose)
// ---------------------------------------------------------------------------
__global__ void prep_w_kernel(const float* __restrict__ w,
                              const float* __restrict__ wm) {
    __shared__ float tile[32][33];
    int n  = blockIdx.z;
    int i0 = blockIdx.x * 32;
    int j0 = blockIdx.y * 32;
    int tx = threadIdx.x, ty = threadIdx.y;   // 32 x 8
    const float* wp = w  + (size_t)n * D_ * D_;
    const float* mp = wm + (size_t)n * D_ * D_;
#pragma unroll
    for (int r = 0; r < 32; r += 8) {
        int j = j0 + ty + r;
        tile[ty + r][tx] = wp[j * D_ + i0 + tx] * mp[j * D_ + i0 + tx];
    }
    __syncthreads();
    float* o = g_wT + (size_t)n * D_ * D_;
#pragma unroll
    for (int r = 0; r < 32; r += 8) {
        int i = i0 + ty + r;
        o[i * D_ + j0 + tx] = tile[tx][ty + r];
    }
}

// ---------------------------------------------------------------------------
// Prep B: masked bias + n_act = popcount(bias_mask row)
// ---------------------------------------------------------------------------
__global__ void prep_b_kernel(const float* __restrict__ b,
                              const float* __restrict__ bm) {
    int n = blockIdx.x, t = threadIdx.x;   // 256 threads
    __shared__ int cnt;
    if (t == 0) cnt = 0;
    __syncthreads();
    float m = bm[n * D_ + t];
    g_bias[n * D_ + t] = b[n * D_ + t] * m;
    unsigned ballot = __ballot_sync(0xFFFFFFFFu, m != 0.0f);
    if ((t & 31) == 0) atomicAdd(&cnt, __popc(ballot));
    __syncthreads();
    if (t == 0) g_nact[n] = cnt;
}

// ---------------------------------------------------------------------------
// Main: per CTA, one group n and a 128-row batch tile. x tile lives in smem
// (transposed [i][m]) across all 4 recurrence steps. w streamed from L2 in
// double-buffered KT x 256 tiles. 8x8 register blocking per thread.
// Warp-level j-skip and k-loop bound at n_act (mask-zero region is a no-op).
// ---------------------------------------------------------------------------
__global__ __launch_bounds__(NTHREADS, 1)
void recur_kernel(const float* __restrict__ x_in, float* __restrict__ out) {
    extern __shared__ float smem[];
    float* xs = smem;                    // [D_][MT]      = 128 KB
    float* ws = xs + D_ * MT;            // [2][KT][D_]   =  32 KB
    float* bs = ws + 2 * KT * D_;        // [D_]          =   1 KB

    int n  = blockIdx.y;
    int m0 = blockIdx.x * MT;
    int t  = threadIdx.x;
    int tx = t >> 4;     // 0..31  (col group of 8; warp spans 32-aligned j range)
    int ty = t & 15;     // 0..15  (row group of 8)

    int nact = g_nact[n];
    if (t < D_) bs[t] = g_bias[n * D_ + t];

    // Load x tile transposed: xs[i][m] = x[(m0+m)*N_ + n][i]
    {
        int m  = t >> 2;
        int i0 = (t & 3) * 64;
        const float4* src =
            (const float4*)(x_in + ((size_t)(m0 + m) * N_ + n) * D_ + i0);
#pragma unroll
        for (int c = 0; c < 16; c++) {
            float4 v = src[c];
            int i = i0 + c * 4;
            xs[(i + 0) * MT + m] = v.x;
            xs[(i + 1) * MT + m] = v.y;
            xs[(i + 2) * MT + m] = v.z;
            xs[(i + 3) * MT + m] = v.w;
        }
    }

    const float* wT = g_wT + (size_t)n * D_ * D_;
    const bool active = (tx * 8) < nact;   // warp-uniform (nact % 32 == 0)
    const int  nk  = nact / KT;
    const int  wkk = t >> 5;               // loader: row within k-tile
    const int  wj0 = (t & 31) * 8;         // loader: col

    for (int step = 0; step < STEPS; step++) {
        float acc[8][8];
#pragma unroll
        for (int i = 0; i < 8; i++)
#pragma unroll
            for (int j = 0; j < 8; j++) acc[i][j] = 0.0f;

        __syncthreads();   // x-load / previous-step update visible
        // preload k-tile 0 into buffer 0
        {
            const float4* s = (const float4*)(wT + wkk * D_ + wj0);
            float4* d = (float4*)(ws + wkk * D_ + wj0);
            d[0] = s[0]; d[1] = s[1];
        }
        __syncthreads();

        for (int kt = 0; kt < nk; kt++) {
            int buf = kt & 1;
            if (kt + 1 < nk) {   // prefetch next tile into the other buffer
                const float4* s =
                    (const float4*)(wT + ((kt + 1) * KT + wkk) * D_ + wj0);
                float4* d =
                    (float4*)(ws + (buf ^ 1) * KT * D_ + wkk * D_ + wj0);
                d[0] = s[0]; d[1] = s[1];
            }
            if (active) {
                const float* wsb = ws + buf * KT * D_;
#pragma unroll
                for (int kk = 0; kk < KT; kk++) {
                    const float* xr = xs + (kt * KT + kk) * MT + ty * 8;
                    float4 a0 = *(const float4*)(xr);
                    float4 a1 = *(const float4*)(xr + 4);
                    const float* wr = wsb + kk * D_ + tx * 8;
                    float4 b0 = *(const float4*)(wr);
                    float4 b1 = *(const float4*)(wr + 4);
                    float a[8] = {a0.x, a0.y, a0.z, a0.w, a1.x, a1.y, a1.z, a1.w};
                    float b[8] = {b0.x, b0.y, b0.z, b0.w, b1.x, b1.y, b1.z, b1.w};
#pragma unroll
                    for (int mi = 0; mi < 8; mi++)
#pragma unroll
                        for (int ji = 0; ji < 8; ji++)
                            acc[mi][ji] = fmaf(a[mi], b[ji], acc[mi][ji]);
                }
            }
            __syncthreads();
        }

        // x += relu(acc + b)   (only active j columns ever change)
        if (active) {
#pragma unroll
            for (int ji = 0; ji < 8; ji++) {
                int j = tx * 8 + ji;
                float bj = bs[j];
#pragma unroll
                for (int mi = 0; mi < 8; mi++) {
                    int m = ty * 8 + mi;
                    float v = fmaxf(acc[mi][ji] + bj, 0.0f);
                    xs[j * MT + m] += v;
                }
            }
        }
        __syncthreads();
    }

    // Write full tile out (cols >= nact are unchanged x, still must be written)
    {
        int m  = t >> 2;
        int i0 = (t & 3) * 64;
        float4* dst = (float4*)(out + ((size_t)(m0 + m) * N_ + n) * D_ + i0);
#pragma unroll
        for (int c = 0; c < 16; c++) {
            int i = i0 + c * 4;
            float4 v;
            v.x = xs[(i + 0) * MT + m];
            v.y = xs[(i + 1) * MT + m];
            v.z = xs[(i + 2) * MT + m];
            v.w = xs[(i + 3) * MT + m];
            dst[c] = v;
        }
    }
}

// ---------------------------------------------------------------------------
extern "C" void kernel_launch(void* const* d_in, const int* in_sizes, int n_in,
                              void* d_out, int out_size) {
    const float* x  = (const float*)d_in[0];
    const float* w  = (const float*)d_in[1];
    const float* b  = (const float*)d_in[2];
    const float* wm = (const float*)d_in[3];
    const float* bm = (const float*)d_in[4];
    float* out = (float*)d_out;

    prep_w_kernel<<<dim3(D_ / 32, D_ / 32, N_), dim3(32, 8)>>>(w, wm);
    prep_b_kernel<<<N_, D_>>>(b, bm);

    const int smem_bytes = (D_ * MT + 2 * KT * D_ + D_) * (int)sizeof(float);
    cudaFuncSetAttribute(recur_kernel,
                         cudaFuncAttributeMaxDynamicSharedMemorySize, smem_bytes);
    recur_kernel<<<dim3(B_ / MT, N_), NTHREADS, smem_bytes>>>(x, out);
}

// round 4
// speedup vs baseline: 1.4135x; 1.4135x over previous
#include <cuda_runtime.h>
#include <cuda_bf16.h>
#include <cstdint>

#define B_ 2048
#define N_ 64
#define D_ 256
#define MT 64
#define NTH 256
#define STEPS 4

// ---------------------------------------------------------------------------
// Device scratch. g_wpk: masked w split into bf16 hi/lo, packed bf16x2:
// index ((n*2+half)*256 + j)*128 + k2   (j = output row, k contiguous)
// ---------------------------------------------------------------------------
__device__ uint32_t g_wpk[(size_t)N_ * 2 * D_ * (D_ / 2)];   // 16 MB
__device__ float    g_bias[N_ * D_];
__device__ int      g_nact[N_];

// split pair of fp32 into packed bf16x2 hi + bf16x2 lo (residual)
__device__ __forceinline__ void split2(float a, float b, uint32_t& hi, uint32_t& lo) {
    __nv_bfloat162 H = __floats2bfloat162_rn(a, b);
    float ra = a - __bfloat162float(H.x);
    float rb = b - __bfloat162float(H.y);
    __nv_bfloat162 L = __floats2bfloat162_rn(ra, rb);
    hi = *reinterpret_cast<uint32_t*>(&H);
    lo = *reinterpret_cast<uint32_t*>(&L);
}

__device__ __forceinline__ uint32_t smem_u32(const void* p) {
    uint32_t a;
    asm("{ .reg .u64 t; cvta.to.shared.u64 t, %1; cvt.u32.u64 %0, t; }"
        : "=r"(a) : "l"(p));
    return a;
}

#define LDSM4(r, addr) \
    asm volatile("ldmatrix.sync.aligned.m8n8.x4.shared.b16 {%0,%1,%2,%3}, [%4];" \
        : "=r"((r)[0]), "=r"((r)[1]), "=r"((r)[2]), "=r"((r)[3]) : "r"(addr))

#define MMA16816(d, a, b0, b1) \
    asm volatile("mma.sync.aligned.m16n8k16.row.col.f32.bf16.bf16.f32 " \
        "{%0,%1,%2,%3}, {%4,%5,%6,%7}, {%8,%9}, {%0,%1,%2,%3};" \
        : "+f"((d)[0]), "+f"((d)[1]), "+f"((d)[2]), "+f"((d)[3]) \
        : "r"((a)[0]), "r"((a)[1]), "r"((a)[2]), "r"((a)[3]), "r"(b0), "r"(b1))

// ---------------------------------------------------------------------------
// Prep A: split masked w -> bf16 hi/lo packed image
// ---------------------------------------------------------------------------
__global__ void prep_w_kernel(const float* __restrict__ w,
                              const float* __restrict__ wm) {
    int n = blockIdx.x;
    int t = threadIdx.x;
    int j = blockIdx.y * 64 + (t & 63);
    int c = t >> 6;
    const float4* wp = (const float4*)(w  + ((size_t)n * D_ + j) * D_) + c * 16;
    const float4* mp = (const float4*)(wm + ((size_t)n * D_ + j) * D_) + c * 16;
    uint32_t* oH = g_wpk + ((size_t)(n * 2 + 0) * D_ + j) * 128 + c * 32;
    uint32_t* oL = g_wpk + ((size_t)(n * 2 + 1) * D_ + j) * 128 + c * 32;
#pragma unroll
    for (int i4 = 0; i4 < 16; i4++) {
        float4 a = wp[i4];
        float4 m = mp[i4];
        uint32_t h0, l0, h1, l1;
        split2(a.x * m.x, a.y * m.y, h0, l0);
        split2(a.z * m.z, a.w * m.w, h1, l1);
        oH[i4 * 2] = h0; oH[i4 * 2 + 1] = h1;
        oL[i4 * 2] = l0; oL[i4 * 2 + 1] = l1;
    }
}

// ---------------------------------------------------------------------------
// Prep B: masked bias + n_act
// ---------------------------------------------------------------------------
__global__ void prep_b_kernel(const float* __restrict__ b,
                              const float* __restrict__ bm) {
    int n = blockIdx.x, t = threadIdx.x;
    __shared__ int cnt;
    if (t == 0) cnt = 0;
    __syncthreads();
    float m = bm[n * D_ + t];
    g_bias[n * D_ + t] = b[n * D_ + t] * m;
    unsigned ballot = __ballot_sync(0xFFFFFFFFu, m != 0.0f);
    if ((t & 31) == 0) atomicAdd(&cnt, __popc(ballot));
    __syncthreads();
    if (t == 0) g_nact[n] = cnt;
}

// ---------------------------------------------------------------------------
// Main: 64-row x tile resident in smem as bf16 hi/lo (row stride 528B).
// w streamed in K-slabs of 32 (hi+lo), register-staged double buffer.
// 8 warps = 2(M) x 4(N); warp tile M=32 N=64; mma.m16n8k16 bf16, fp32 acc.
// Per k16 per warp: 48 HMMA (3 split terms x 2m x 8n), 12 LDSM.x4.
// ---------------------------------------------------------------------------
// smem offsets (bytes)
#define XSTR    528
#define OFF_XH  0u
#define OFF_XL  33792u
#define OFF_W   67584u          // [buf2][half2: +0 hi / +20480 lo][256 rows * 80B]
#define WBUF    40960u
#define WHALF   20480u
#define OFF_BS  149504u
#define SMEM_SZ 150528

__global__ __launch_bounds__(NTH, 1)
void recur_kernel(const float* __restrict__ x_in, float* __restrict__ out) {
    extern __shared__ char smem[];
    uint32_t sb = smem_u32(smem);
    int n  = blockIdx.y;
    int m0 = blockIdx.x * MT;
    int t  = threadIdx.x;
    int l  = t & 31;
    int wid = t >> 5;
    int warp_m = wid >> 2;      // 0..1
    int warp_n = wid & 3;       // 0..3

    int nact = g_nact[n];
    ((float*)(smem + OFF_BS))[t] = g_bias[n * D_ + t];

    // ---- initial x load + split into hi/lo bf16 tiles ----
    {
        int m = t >> 2, q = t & 3;
        const float4* src =
            (const float4*)(x_in + ((size_t)(m0 + m) * N_ + n) * D_) + q * 16;
        char* rowH = smem + OFF_XH + m * XSTR;
        char* rowL = smem + OFF_XL + m * XSTR;
#pragma unroll
        for (int c = 0; c < 16; c++) {
            float4 v = src[c];
            int k = q * 64 + c * 4;
            uint32_t h0, l0, h1, l1;
            split2(v.x, v.y, h0, l0);
            split2(v.z, v.w, h1, l1);
            *(uint32_t*)(rowH + k * 2)     = h0;
            *(uint32_t*)(rowL + k * 2)     = l0;
            *(uint32_t*)(rowH + k * 2 + 4) = h1;
            *(uint32_t*)(rowL + k * 2 + 4) = l1;
        }
    }

    const int nslab = nact >> 5;          // K-slabs of 32
    const int total = STEPS * nslab;
    const float4* wsrc = (const float4*)g_wpk;
    const bool ldr = (t < nact);          // thread t loads w row j=t
    const size_t srcH = ((size_t)(n * 2 + 0) * D_ + t) * 32;   // float4 units
    const size_t srcL = ((size_t)(n * 2 + 1) * D_ + t) * 32;

    // preload slab 0 -> buffer 0
    if (ldr) {
        char* dH = smem + OFF_W + t * 80;
        char* dL = smem + OFF_W + WHALF + t * 80;
#pragma unroll
        for (int q = 0; q < 4; q++) {
            *(float4*)(dH + q * 16) = wsrc[srcH + q];
            *(float4*)(dL + q * 16) = wsrc[srcL + q];
        }
    }
    __syncthreads();

    // per-lane ldmatrix base addresses
    const uint32_t aBaseH = sb + OFF_XH + (uint32_t)(warp_m * 32 + (l & 15)) * XSTR
                            + (uint32_t)(l >> 4) * 16;
    const uint32_t aBaseL = aBaseH + (OFF_XL - OFF_XH);
    const uint32_t bBase  = sb + OFF_W
                            + (uint32_t)((l & 7) + ((l >> 4) & 1) * 8) * 80
                            + (uint32_t)((l >> 3) & 1) * 16;

    float acc[2][8][4];
    float4 pre[8];

    for (int g = 0; g < total; g++) {
        int buf = g & 1;
        int s = g % nslab;
        if (s == 0) {
#pragma unroll
            for (int i = 0; i < 2; i++)
#pragma unroll
                for (int jn = 0; jn < 8; jn++)
#pragma unroll
                    for (int r = 0; r < 4; r++) acc[i][jn][r] = 0.0f;
        }

        // register-stage prefetch of next slab (LDG issues before MMA block)
        int sn = (g + 1) % nslab;
        bool pf = (g + 1 < total) && ldr;
        if (pf) {
#pragma unroll
            for (int q = 0; q < 4; q++) {
                pre[q]     = wsrc[srcH + (size_t)sn * 4 + q];
                pre[4 + q] = wsrc[srcL + (size_t)sn * 4 + q];
            }
        }

        // ---- compute on buffer `buf` ----
        const uint32_t wOff = (uint32_t)buf * WBUF;
        const int kbase = s * 32;
#pragma unroll
        for (int kh = 0; kh < 2; kh++) {
            uint32_t aoff = (uint32_t)(kbase + kh * 16) * 2;
            uint32_t aH0[4], aH1[4], aL0[4], aL1[4];
            LDSM4(aH0, aBaseH + aoff);
            LDSM4(aH1, aBaseH + 8448 + aoff);
            LDSM4(aL0, aBaseL + aoff);
            LDSM4(aL1, aBaseL + 8448 + aoff);
            uint32_t klb = (uint32_t)kh * 32;
#pragma unroll
            for (int p = 0; p < 4; p++) {
                int n0 = warp_n * 64 + p * 16;
                if (n0 < nact) {
                    uint32_t bH[4], bL[4];
                    uint32_t boff = wOff + (uint32_t)n0 * 80 + klb;
                    LDSM4(bH, bBase + boff);
                    LDSM4(bL, bBase + boff + WHALF);
                    MMA16816(acc[0][2 * p],     aH0, bH[0], bH[1]);
                    MMA16816(acc[0][2 * p + 1], aH0, bH[2], bH[3]);
                    MMA16816(acc[1][2 * p],     aH1, bH[0], bH[1]);
                    MMA16816(acc[1][2 * p + 1], aH1, bH[2], bH[3]);
                    MMA16816(acc[0][2 * p],     aL0, bH[0], bH[1]);
                    MMA16816(acc[0][2 * p + 1], aL0, bH[2], bH[3]);
                    MMA16816(acc[1][2 * p],     aL1, bH[0], bH[1]);
                    MMA16816(acc[1][2 * p + 1], aL1, bH[2], bH[3]);
                    MMA16816(acc[0][2 * p],     aH0, bL[0], bL[1]);
                    MMA16816(acc[0][2 * p + 1], aH0, bL[2], bL[3]);
                    MMA16816(acc[1][2 * p],     aH1, bL[0], bL[1]);
                    MMA16816(acc[1][2 * p + 1], aH1, bL[2], bL[3]);
                }
            }
        }

        // commit prefetched slab into the other buffer
        if (pf) {
            char* dH = smem + OFF_W + (buf ^ 1) * WBUF + t * 80;
            char* dL = dH + WHALF;
#pragma unroll
            for (int q = 0; q < 4; q++) {
                *(float4*)(dH + q * 16) = pre[q];
                *(float4*)(dL + q * 16) = pre[4 + q];
            }
        }

        if (s == nslab - 1) {
            __syncthreads();   // all warps done reading x tiles
            // ---- epilogue: x += relu(acc + b), re-split into hi/lo ----
            const float* bsp = (const float*)(smem + OFF_BS);
            int q4 = l >> 2, tc = l & 3;
#pragma unroll
            for (int mt = 0; mt < 2; mt++) {
                int mrow = warp_m * 32 + mt * 16 + q4;
#pragma unroll
                for (int nt = 0; nt < 8; nt++) {
                    int j0 = warp_n * 64 + nt * 8;
                    if (j0 >= nact) continue;
                    int j = j0 + tc * 2;
                    float b0 = bsp[j], b1 = bsp[j + 1];
#pragma unroll
                    for (int half = 0; half < 2; half++) {
                        int m = mrow + half * 8;
                        uint32_t off = (uint32_t)m * XSTR + (uint32_t)j * 2;
                        uint32_t h  = *(uint32_t*)(smem + OFF_XH + off);
                        uint32_t lo = *(uint32_t*)(smem + OFF_XL + off);
                        __nv_bfloat162 H = *(__nv_bfloat162*)&h;
                        __nv_bfloat162 L = *(__nv_bfloat162*)&lo;
                        float c0 = acc[mt][nt][half * 2];
                        float c1 = acc[mt][nt][half * 2 + 1];
                        float x0 = __bfloat162float(H.x) + __bfloat162float(L.x)
                                   + fmaxf(c0 + b0, 0.0f);
                        float x1 = __bfloat162float(H.y) + __bfloat162float(L.y)
                                   + fmaxf(c1 + b1, 0.0f);
                        uint32_t nh, nl;
                        split2(x0, x1, nh, nl);
                        *(uint32_t*)(smem + OFF_XH + off) = nh;
                        *(uint32_t*)(smem + OFF_XL + off) = nl;
                    }
                }
            }
            __syncthreads();   // epilogue + STS visible before next step
        } else {
            __syncthreads();   // buffer handoff
        }
    }

    // ---- final store: x = hi + lo ----
    {
        int m = t >> 2, q = t & 3;
        float4* dst = (float4*)(out + ((size_t)(m0 + m) * N_ + n) * D_) + q * 16;
        const char* rowH = smem + OFF_XH + m * XSTR;
        const char* rowL = smem + OFF_XL + m * XSTR;
#pragma unroll
        for (int c = 0; c < 16; c++) {
            int k = q * 64 + c * 4;
            uint32_t h0  = *(const uint32_t*)(rowH + k * 2);
            uint32_t l0  = *(const uint32_t*)(rowL + k * 2);
            uint32_t h1  = *(const uint32_t*)(rowH + k * 2 + 4);
            uint32_t l1  = *(const uint32_t*)(rowL + k * 2 + 4);
            __nv_bfloat162 H0 = *(__nv_bfloat162*)&h0, L0 = *(__nv_bfloat162*)&l0;
            __nv_bfloat162 H1 = *(__nv_bfloat162*)&h1, L1 = *(__nv_bfloat162*)&l1;
            float4 v;
            v.x = __bfloat162float(H0.x) + __bfloat162float(L0.x);
            v.y = __bfloat162float(H0.y) + __bfloat162float(L0.y);
            v.z = __bfloat162float(H1.x) + __bfloat162float(L1.x);
            v.w = __bfloat162float(H1.y) + __bfloat162float(L1.y);
            dst[c] = v;
        }
    }
}

// ---------------------------------------------------------------------------
extern "C" void kernel_launch(void* const* d_in, const int* in_sizes, int n_in,
                              void* d_out, int out_size) {
    const float* x  = (const float*)d_in[0];
    const float* w  = (const float*)d_in[1];
    const float* b  = (const float*)d_in[2];
    const float* wm = (const float*)d_in[3];
    const float* bm = (const float*)d_in[4];
    float* out = (float*)d_out;

    prep_w_kernel<<<dim3(N_, 4), 256>>>(w, wm);
    prep_b_kernel<<<N_, D_>>>(b, bm);

    cudaFuncSetAttribute(recur_kernel,
                         cudaFuncAttributeMaxDynamicSharedMemorySize, SMEM_SZ);
    recur_kernel<<<dim3(B_ / MT, N_), NTH, SMEM_SZ>>>(x, out);
}

// round 5
// speedup vs baseline: 1.7413x; 1.2319x over previous
#include <cuda_runtime.h>
#include <cuda_bf16.h>
#include <cstdint>

#define B_ 2048
#define N_ 64
#define D_ 256
#define MT 64
#define NTH 256
#define STEPS 4

// ---------------------------------------------------------------------------
// w image, slab-major: [n][slab(16)][half(hi/lo)][row(256)][16k * bf16 = 32B]
// Each (n, slab, half) block = 256 rows x 32 B contiguous -> coalesced loads.
// ---------------------------------------------------------------------------
__device__ uint32_t g_w[(size_t)N_ * 16 * 2 * D_ * 8];   // 16 MB
__device__ float    g_bias[N_ * D_];
__device__ int      g_nact[N_];

// split pair of fp32 into packed bf16x2 hi + bf16x2 lo (residual)
__device__ __forceinline__ void split2(float a, float b, uint32_t& hi, uint32_t& lo) {
    __nv_bfloat162 H = __floats2bfloat162_rn(a, b);
    float ra = a - __bfloat162float(H.x);
    float rb = b - __bfloat162float(H.y);
    __nv_bfloat162 L = __floats2bfloat162_rn(ra, rb);
    hi = *reinterpret_cast<uint32_t*>(&H);
    lo = *reinterpret_cast<uint32_t*>(&L);
}

__device__ __forceinline__ uint32_t smem_u32(const void* p) {
    uint32_t a;
    asm("{ .reg .u64 t; cvta.to.shared.u64 t, %1; cvt.u32.u64 %0, t; }"
        : "=r"(a) : "l"(p));
    return a;
}

#define LDSM4(r, addr) \
    asm volatile("ldmatrix.sync.aligned.m8n8.x4.shared.b16 {%0,%1,%2,%3}, [%4];" \
        : "=r"((r)[0]), "=r"((r)[1]), "=r"((r)[2]), "=r"((r)[3]) : "r"(addr))

#define MMA16816(d, a, b0, b1) \
    asm volatile("mma.sync.aligned.m16n8k16.row.col.f32.bf16.bf16.f32 " \
        "{%0,%1,%2,%3}, {%4,%5,%6,%7}, {%8,%9}, {%0,%1,%2,%3};" \
        : "+f"((d)[0]), "+f"((d)[1]), "+f"((d)[2]), "+f"((d)[3]) \
        : "r"((a)[0]), "r"((a)[1]), "r"((a)[2]), "r"((a)[3]), "r"(b0), "r"(b1))

// ---------------------------------------------------------------------------
// Prep A: split masked w -> slab-major bf16 hi/lo image
// ---------------------------------------------------------------------------
__global__ void prep_w_kernel(const float* __restrict__ w,
                              const float* __restrict__ wm) {
    int n = blockIdx.x;
    int t = threadIdx.x;
    int j = blockIdx.y * 64 + (t & 63);
    int c = t >> 6;                       // k range [c*64, c*64+64)
    const float4* wp = (const float4*)(w  + ((size_t)n * D_ + j) * D_) + c * 16;
    const float4* mp = (const float4*)(wm + ((size_t)n * D_ + j) * D_) + c * 16;
#pragma unroll
    for (int i4 = 0; i4 < 16; i4++) {
        float4 a = wp[i4];
        float4 m = mp[i4];
        uint32_t h0, l0, h1, l1;
        split2(a.x * m.x, a.y * m.y, h0, l0);
        split2(a.z * m.z, a.w * m.w, h1, l1);
        int k = c * 64 + i4 * 4;
        int s = k >> 4;
        int q = (k & 15) >> 1;            // uint32 index within 32B row chunk
        uint32_t* oH = g_w + ((((size_t)n * 16 + s) * 2 + 0) * D_ + j) * 8 + q;
        uint32_t* oL = g_w + ((((size_t)n * 16 + s) * 2 + 1) * D_ + j) * 8 + q;
        oH[0] = h0; oH[1] = h1;
        oL[0] = l0; oL[1] = l1;
    }
}

// ---------------------------------------------------------------------------
// Prep B: masked bias + n_act
// ---------------------------------------------------------------------------
__global__ void prep_b_kernel(const float* __restrict__ b,
                              const float* __restrict__ bm) {
    int n = blockIdx.x, t = threadIdx.x;
    __shared__ int cnt;
    if (t == 0) cnt = 0;
    __syncthreads();
    float m = bm[n * D_ + t];
    g_bias[n * D_ + t] = b[n * D_ + t] * m;
    unsigned ballot = __ballot_sync(0xFFFFFFFFu, m != 0.0f);
    if ((t & 31) == 0) atomicAdd(&cnt, __popc(ballot));
    __syncthreads();
    if (t == 0) g_nact[n] = cnt;
}

// ---------------------------------------------------------------------------
// Main: 64-row x tile resident in smem as bf16 hi/lo (row stride 528B).
// w streamed in K-slabs of 16 (hi+lo, 16KB/slab), register-staged double
// buffer, coalesced. 8 warps = 2(M) x 4(N); warp tile M=32 N=64.
// smem = 101376B -> 2 CTAs/SM (4 warps/SMSP).
// ---------------------------------------------------------------------------
#define XSTR    528
#define OFF_XH  0u
#define OFF_XL  33792u
#define OFF_W   67584u          // [buf2][hi 8192 | lo 8192]
#define WBUF    16384u
#define WHALF   8192u
#define OFF_BS  100352u
#define SMEM_SZ 101376

__global__ __launch_bounds__(NTH, 2)
void recur_kernel(const float* __restrict__ x_in, float* __restrict__ out) {
    extern __shared__ char smem[];
    uint32_t sb = smem_u32(smem);
    int n  = blockIdx.y;
    int m0 = blockIdx.x * MT;
    int t  = threadIdx.x;
    int l  = t & 31;
    int wid = t >> 5;
    int warp_m = wid >> 2;      // 0..1
    int warp_n = wid & 3;       // 0..3

    int nact = g_nact[n];
    ((float*)(smem + OFF_BS))[t] = g_bias[n * D_ + t];

    // ---- initial x load + split into hi/lo bf16 tiles ----
    {
        int m = t >> 2, q = t & 3;
        const float4* src =
            (const float4*)(x_in + ((size_t)(m0 + m) * N_ + n) * D_) + q * 16;
        char* rowH = smem + OFF_XH + m * XSTR;
        char* rowL = smem + OFF_XL + m * XSTR;
#pragma unroll
        for (int c = 0; c < 16; c++) {
            float4 v = src[c];
            int k = q * 64 + c * 4;
            uint32_t h0, l0, h1, l1;
            split2(v.x, v.y, h0, l0);
            split2(v.z, v.w, h1, l1);
            *(uint32_t*)(rowH + k * 2)     = h0;
            *(uint32_t*)(rowL + k * 2)     = l0;
            *(uint32_t*)(rowH + k * 2 + 4) = h1;
            *(uint32_t*)(rowL + k * 2 + 4) = l1;
        }
    }

    const int nslab = nact >> 4;          // K-slabs of 16
    const int total = STEPS * nslab;
    const float4* wsrc = (const float4*)g_w;
    const bool ldr = (t < nact);          // thread t loads w row j=t (32B hi+lo)
    // float4 index of (n, slab s, half h, row t): (((n*16+s)*2+h)*256 + t)*2

    // preload slab 0 -> buffer 0
    if (ldr) {
        size_t iH = (((size_t)n * 16 + 0) * 2 + 0) * D_ + t;
        size_t iL = (((size_t)n * 16 + 0) * 2 + 1) * D_ + t;
        float4* dH = (float4*)(smem + OFF_W + t * 32);
        float4* dL = (float4*)(smem + OFF_W + WHALF + t * 32);
        dH[0] = wsrc[iH * 2];     dH[1] = wsrc[iH * 2 + 1];
        dL[0] = wsrc[iL * 2];     dL[1] = wsrc[iL * 2 + 1];
    }
    __syncthreads();

    // per-lane ldmatrix base addresses
    const uint32_t aBaseH = sb + OFF_XH + (uint32_t)(warp_m * 32 + (l & 15)) * XSTR
                            + (uint32_t)(l >> 4) * 16;
    const uint32_t aBaseL = aBaseH + (OFF_XL - OFF_XH);
    const uint32_t bBase  = sb + OFF_W
                            + (uint32_t)((l & 7) + ((l >> 4) & 1) * 8) * 32
                            + (uint32_t)((l >> 3) & 1) * 16;

    float acc[2][8][4];
    float4 pre[4];

    for (int g = 0; g < total; g++) {
        int buf = g & 1;
        int s = g % nslab;
        if (s == 0) {
#pragma unroll
            for (int i = 0; i < 2; i++)
#pragma unroll
                for (int jn = 0; jn < 8; jn++)
#pragma unroll
                    for (int r = 0; r < 4; r++) acc[i][jn][r] = 0.0f;
        }

        // register-stage prefetch of next slab (coalesced 16KB stream)
        int sn = (g + 1) % nslab;
        bool pf = (g + 1 < total) && ldr;
        if (pf) {
            size_t iH = (((size_t)n * 16 + sn) * 2 + 0) * D_ + t;
            size_t iL = (((size_t)n * 16 + sn) * 2 + 1) * D_ + t;
            pre[0] = wsrc[iH * 2];  pre[1] = wsrc[iH * 2 + 1];
            pre[2] = wsrc[iL * 2];  pre[3] = wsrc[iL * 2 + 1];
        }

        // ---- compute on buffer `buf` (one k16 per slab) ----
        {
            uint32_t aoff = (uint32_t)s * 32;   // k = s*16 -> byte k*2
            uint32_t aH0[4], aH1[4], aL0[4], aL1[4];
            LDSM4(aH0, aBaseH + aoff);
            LDSM4(aH1, aBaseH + 8448 + aoff);   // +16 rows
            LDSM4(aL0, aBaseL + aoff);
            LDSM4(aL1, aBaseL + 8448 + aoff);
            const uint32_t wOff = (uint32_t)buf * WBUF;
#pragma unroll
            for (int p = 0; p < 4; p++) {
                int n0 = warp_n * 64 + p * 16;
                if (n0 < nact) {
                    uint32_t bH[4], bL[4];
                    uint32_t boff = wOff + (uint32_t)n0 * 32;
                    LDSM4(bH, bBase + boff);
                    LDSM4(bL, bBase + boff + WHALF);
                    MMA16816(acc[0][2 * p],     aH0, bH[0], bH[1]);
                    MMA16816(acc[0][2 * p + 1], aH0, bH[2], bH[3]);
                    MMA16816(acc[1][2 * p],     aH1, bH[0], bH[1]);
                    MMA16816(acc[1][2 * p + 1], aH1, bH[2], bH[3]);
                    MMA16816(acc[0][2 * p],     aL0, bH[0], bH[1]);
                    MMA16816(acc[0][2 * p + 1], aL0, bH[2], bH[3]);
                    MMA16816(acc[1][2 * p],     aL1, bH[0], bH[1]);
                    MMA16816(acc[1][2 * p + 1], aL1, bH[2], bH[3]);
                    MMA16816(acc[0][2 * p],     aH0, bL[0], bL[1]);
                    MMA16816(acc[0][2 * p + 1], aH0, bL[2], bL[3]);
                    MMA16816(acc[1][2 * p],     aH1, bL[0], bL[1]);
                    MMA16816(acc[1][2 * p + 1], aH1, bL[2], bL[3]);
                }
            }
        }

        // commit prefetched slab into the other buffer
        if (pf) {
            float4* dH = (float4*)(smem + OFF_W + (buf ^ 1) * WBUF + t * 32);
            float4* dL = (float4*)(smem + OFF_W + (buf ^ 1) * WBUF + WHALF + t * 32);
            dH[0] = pre[0]; dH[1] = pre[1];
            dL[0] = pre[2]; dL[1] = pre[3];
        }

        if (s == nslab - 1) {
            __syncthreads();   // all warps done reading x tiles
            // ---- epilogue: x += relu(acc + b), re-split into hi/lo ----
            const float* bsp = (const float*)(smem + OFF_BS);
            int q4 = l >> 2, tc = l & 3;
#pragma unroll
            for (int mt = 0; mt < 2; mt++) {
                int mrow = warp_m * 32 + mt * 16 + q4;
#pragma unroll
                for (int nt = 0; nt < 8; nt++) {
                    int j0 = warp_n * 64 + nt * 8;
                    if (j0 >= nact) continue;
                    int j = j0 + tc * 2;
                    float b0 = bsp[j], b1 = bsp[j + 1];
#pragma unroll
                    for (int half = 0; half < 2; half++) {
                        int m = mrow + half * 8;
                        uint32_t off = (uint32_t)m * XSTR + (uint32_t)j * 2;
                        uint32_t h  = *(uint32_t*)(smem + OFF_XH + off);
                        uint32_t lo = *(uint32_t*)(smem + OFF_XL + off);
                        __nv_bfloat162 H = *(__nv_bfloat162*)&h;
                        __nv_bfloat162 L = *(__nv_bfloat162*)&lo;
                        float c0 = acc[mt][nt][half * 2];
                        float c1 = acc[mt][nt][half * 2 + 1];
                        float x0 = __bfloat162float(H.x) + __bfloat162float(L.x)
                                   + fmaxf(c0 + b0, 0.0f);
                        float x1 = __bfloat162float(H.y) + __bfloat162float(L.y)
                                   + fmaxf(c1 + b1, 0.0f);
                        uint32_t nh, nl;
                        split2(x0, x1, nh, nl);
                        *(uint32_t*)(smem + OFF_XH + off) = nh;
                        *(uint32_t*)(smem + OFF_XL + off) = nl;
                    }
                }
            }
            __syncthreads();   // epilogue visible before next step
        } else {
            __syncthreads();   // buffer handoff
        }
    }

    // ---- final store: x = hi + lo ----
    {
        int m = t >> 2, q = t & 3;
        float4* dst = (float4*)(out + ((size_t)(m0 + m) * N_ + n) * D_) + q * 16;
        const char* rowH = smem + OFF_XH + m * XSTR;
        const char* rowL = smem + OFF_XL + m * XSTR;
#pragma unroll
        for (int c = 0; c < 16; c++) {
            int k = q * 64 + c * 4;
            uint32_t h0  = *(const uint32_t*)(rowH + k * 2);
            uint32_t l0  = *(const uint32_t*)(rowL + k * 2);
            uint32_t h1  = *(const uint32_t*)(rowH + k * 2 + 4);
            uint32_t l1  = *(const uint32_t*)(rowL + k * 2 + 4);
            __nv_bfloat162 H0 = *(__nv_bfloat162*)&h0, L0 = *(__nv_bfloat162*)&l0;
            __nv_bfloat162 H1 = *(__nv_bfloat162*)&h1, L1 = *(__nv_bfloat162*)&l1;
            float4 v;
            v.x = __bfloat162float(H0.x) + __bfloat162float(L0.x);
            v.y = __bfloat162float(H0.y) + __bfloat162float(L0.y);
            v.z = __bfloat162float(H1.x) + __bfloat162float(L1.x);
            v.w = __bfloat162float(H1.y) + __bfloat162float(L1.y);
            dst[c] = v;
        }
    }
}

// ---------------------------------------------------------------------------
extern "C" void kernel_launch(void* const* d_in, const int* in_sizes, int n_in,
                              void* d_out, int out_size) {
    const float* x  = (const float*)d_in[0];
    const float* w  = (const float*)d_in[1];
    const float* b  = (const float*)d_in[2];
    const float* wm = (const float*)d_in[3];
    const float* bm = (const float*)d_in[4];
    float* out = (float*)d_out;

    prep_w_kernel<<<dim3(N_, 4), 256>>>(w, wm);
    prep_b_kernel<<<N_, D_>>>(b, bm);

    cudaFuncSetAttribute(recur_kernel,
                         cudaFuncAttributeMaxDynamicSharedMemorySize, SMEM_SZ);
    recur_kernel<<<dim3(B_ / MT, N_), NTH, SMEM_SZ>>>(x, out);
}

// round 6
// speedup vs baseline: 1.8531x; 1.0642x over previous
#include <cuda_runtime.h>
#include <cuda_bf16.h>
#include <cstdint>

#define B_ 2048
#define N_ 64
#define D_ 256
#define MT 64
#define NTH 256
#define STEPS 4

// ---------------------------------------------------------------------------
// w image, slab-major: [n][slab(16)][half(hi/lo)][row(256)][16k * bf16 = 32B]
// ---------------------------------------------------------------------------
__device__ uint32_t g_w[(size_t)N_ * 16 * 2 * D_ * 8];   // 16 MB
__device__ float    g_bias[N_ * D_];
__device__ int      g_nact[N_];

__device__ __forceinline__ void split2(float a, float b, uint32_t& hi, uint32_t& lo) {
    __nv_bfloat162 H = __floats2bfloat162_rn(a, b);
    float ra = a - __bfloat162float(H.x);
    float rb = b - __bfloat162float(H.y);
    __nv_bfloat162 L = __floats2bfloat162_rn(ra, rb);
    hi = *reinterpret_cast<uint32_t*>(&H);
    lo = *reinterpret_cast<uint32_t*>(&L);
}

__device__ __forceinline__ uint32_t smem_u32(const void* p) {
    uint32_t a;
    asm("{ .reg .u64 t; cvta.to.shared.u64 t, %1; cvt.u32.u64 %0, t; }"
        : "=r"(a) : "l"(p));
    return a;
}

#define LDSM4(r, addr) \
    asm volatile("ldmatrix.sync.aligned.m8n8.x4.shared.b16 {%0,%1,%2,%3}, [%4];" \
        : "=r"((r)[0]), "=r"((r)[1]), "=r"((r)[2]), "=r"((r)[3]) : "r"(addr))

#define MMA16816(d, a, b0, b1) \
    asm volatile("mma.sync.aligned.m16n8k16.row.col.f32.bf16.bf16.f32 " \
        "{%0,%1,%2,%3}, {%4,%5,%6,%7}, {%8,%9}, {%0,%1,%2,%3};" \
        : "+f"((d)[0]), "+f"((d)[1]), "+f"((d)[2]), "+f"((d)[3]) \
        : "r"((a)[0]), "r"((a)[1]), "r"((a)[2]), "r"((a)[3]), "r"(b0), "r"(b1))

// ---------------------------------------------------------------------------
__global__ void prep_w_kernel(const float* __restrict__ w,
                              const float* __restrict__ wm) {
    int n = blockIdx.x;
    int t = threadIdx.x;
    int j = blockIdx.y * 64 + (t & 63);
    int c = t >> 6;
    const float4* wp = (const float4*)(w  + ((size_t)n * D_ + j) * D_) + c * 16;
    const float4* mp = (const float4*)(wm + ((size_t)n * D_ + j) * D_) + c * 16;
#pragma unroll
    for (int i4 = 0; i4 < 16; i4++) {
        float4 a = wp[i4];
        float4 m = mp[i4];
        uint32_t h0, l0, h1, l1;
        split2(a.x * m.x, a.y * m.y, h0, l0);
        split2(a.z * m.z, a.w * m.w, h1, l1);
        int k = c * 64 + i4 * 4;
        int s = k >> 4;
        int q = (k & 15) >> 1;
        uint32_t* oH = g_w + ((((size_t)n * 16 + s) * 2 + 0) * D_ + j) * 8 + q;
        uint32_t* oL = g_w + ((((size_t)n * 16 + s) * 2 + 1) * D_ + j) * 8 + q;
        oH[0] = h0; oH[1] = h1;
        oL[0] = l0; oL[1] = l1;
    }
}

__global__ void prep_b_kernel(const float* __restrict__ b,
                              const float* __restrict__ bm) {
    int n = blockIdx.x, t = threadIdx.x;
    __shared__ int cnt;
    if (t == 0) cnt = 0;
    __syncthreads();
    float m = bm[n * D_ + t];
    g_bias[n * D_ + t] = b[n * D_ + t] * m;
    unsigned ballot = __ballot_sync(0xFFFFFFFFu, m != 0.0f);
    if ((t & 31) == 0) atomicAdd(&cnt, __popc(ballot));
    __syncthreads();
    if (t == 0) g_nact[n] = cnt;
}

// ---------------------------------------------------------------------------
// Main. Warp j-mapping is INTERLEAVED for SMSP balance:
//   p-tile p of warp (warp_m, warp_n) covers j in [p*64 + warp_n*16, +16).
// For every nact class all 4 warp_n stripes stay (nearly) equally loaded,
// so the per-slab __syncthreads critical path and the per-SMSP tensor load
// are both balanced.
// ---------------------------------------------------------------------------
#define XSTR    528
#define OFF_XH  0u
#define OFF_XL  33792u
#define OFF_W   67584u
#define WBUF    16384u
#define WHALF   8192u
#define OFF_BS  100352u
#define SMEM_SZ 101376

__global__ __launch_bounds__(NTH, 2)
void recur_kernel(const float* __restrict__ x_in, float* __restrict__ out) {
    extern __shared__ char smem[];
    uint32_t sb = smem_u32(smem);
    int n  = blockIdx.y;
    int m0 = blockIdx.x * MT;
    int t  = threadIdx.x;
    int l  = t & 31;
    int wid = t >> 5;
    int warp_m = wid >> 2;
    int warp_n = wid & 3;

    int nact = g_nact[n];
    ((float*)(smem + OFF_BS))[t] = g_bias[n * D_ + t];

    // ---- initial x load + split ----
    {
        int m = t >> 2, q = t & 3;
        const float4* src =
            (const float4*)(x_in + ((size_t)(m0 + m) * N_ + n) * D_) + q * 16;
        char* rowH = smem + OFF_XH + m * XSTR;
        char* rowL = smem + OFF_XL + m * XSTR;
#pragma unroll
        for (int c = 0; c < 16; c++) {
            float4 v = src[c];
            int k = q * 64 + c * 4;
            uint32_t h0, l0, h1, l1;
            split2(v.x, v.y, h0, l0);
            split2(v.z, v.w, h1, l1);
            *(uint32_t*)(rowH + k * 2)     = h0;
            *(uint32_t*)(rowL + k * 2)     = l0;
            *(uint32_t*)(rowH + k * 2 + 4) = h1;
            *(uint32_t*)(rowL + k * 2 + 4) = l1;
        }
    }

    const int nslab = nact >> 4;
    const int total = STEPS * nslab;
    const float4* wsrc = (const float4*)g_w;
    const bool ldr = (t < nact);

    if (ldr) {
        size_t iH = (((size_t)n * 16 + 0) * 2 + 0) * D_ + t;
        size_t iL = (((size_t)n * 16 + 0) * 2 + 1) * D_ + t;
        float4* dH = (float4*)(smem + OFF_W + t * 32);
        float4* dL = (float4*)(smem + OFF_W + WHALF + t * 32);
        dH[0] = wsrc[iH * 2];     dH[1] = wsrc[iH * 2 + 1];
        dL[0] = wsrc[iL * 2];     dL[1] = wsrc[iL * 2 + 1];
    }
    __syncthreads();

    const uint32_t aBaseH = sb + OFF_XH + (uint32_t)(warp_m * 32 + (l & 15)) * XSTR
                            + (uint32_t)(l >> 4) * 16;
    const uint32_t aBaseL = aBaseH + (OFF_XL - OFF_XH);
    const uint32_t bBase  = sb + OFF_W
                            + (uint32_t)((l & 7) + ((l >> 4) & 1) * 8) * 32
                            + (uint32_t)((l >> 3) & 1) * 16;

    float acc[2][8][4];
    float4 pre[4];

    for (int g = 0; g < total; g++) {
        int buf = g & 1;
        int s = g % nslab;
        if (s == 0) {
#pragma unroll
            for (int i = 0; i < 2; i++)
#pragma unroll
                for (int jn = 0; jn < 8; jn++)
#pragma unroll
                    for (int r = 0; r < 4; r++) acc[i][jn][r] = 0.0f;
        }

        int sn = (g + 1) % nslab;
        bool pf = (g + 1 < total) && ldr;
        if (pf) {
            size_t iH = (((size_t)n * 16 + sn) * 2 + 0) * D_ + t;
            size_t iL = (((size_t)n * 16 + sn) * 2 + 1) * D_ + t;
            pre[0] = wsrc[iH * 2];  pre[1] = wsrc[iH * 2 + 1];
            pre[2] = wsrc[iL * 2];  pre[3] = wsrc[iL * 2 + 1];
        }

        // ---- compute on buffer `buf` (one k16 per slab) ----
        {
            uint32_t aoff = (uint32_t)s * 32;
            uint32_t aH0[4], aH1[4], aL0[4], aL1[4];
            LDSM4(aH0, aBaseH + aoff);
            LDSM4(aH1, aBaseH + 8448 + aoff);
            LDSM4(aL0, aBaseL + aoff);
            LDSM4(aL1, aBaseL + 8448 + aoff);
            const uint32_t wOff = (uint32_t)buf * WBUF;
#pragma unroll
            for (int p = 0; p < 4; p++) {
                int n0 = p * 64 + warp_n * 16;   // interleaved stripe
                if (n0 < nact) {
                    uint32_t bH[4], bL[4];
                    uint32_t boff = wOff + (uint32_t)n0 * 32;
                    LDSM4(bH, bBase + boff);
                    LDSM4(bL, bBase + boff + WHALF);
                    MMA16816(acc[0][2 * p],     aH0, bH[0], bH[1]);
                    MMA16816(acc[0][2 * p + 1], aH0, bH[2], bH[3]);
                    MMA16816(acc[1][2 * p],     aH1, bH[0], bH[1]);
                    MMA16816(acc[1][2 * p + 1], aH1, bH[2], bH[3]);
                    MMA16816(acc[0][2 * p],     aL0, bH[0], bH[1]);
                    MMA16816(acc[0][2 * p + 1], aL0, bH[2], bH[3]);
                    MMA16816(acc[1][2 * p],     aL1, bH[0], bH[1]);
                    MMA16816(acc[1][2 * p + 1], aL1, bH[2], bH[3]);
                    MMA16816(acc[0][2 * p],     aH0, bL[0], bL[1]);
                    MMA16816(acc[0][2 * p + 1], aH0, bL[2], bL[3]);
                    MMA16816(acc[1][2 * p],     aH1, bL[0], bL[1]);
                    MMA16816(acc[1][2 * p + 1], aH1, bL[2], bL[3]);
                }
            }
        }

        if (pf) {
            float4* dH = (float4*)(smem + OFF_W + (buf ^ 1) * WBUF + t * 32);
            float4* dL = (float4*)(smem + OFF_W + (buf ^ 1) * WBUF + WHALF + t * 32);
            dH[0] = pre[0]; dH[1] = pre[1];
            dL[0] = pre[2]; dL[1] = pre[3];
        }

        if (s == nslab - 1) {
            __syncthreads();
            // ---- epilogue: x += relu(acc + b) over this warp's stripes ----
            const float* bsp = (const float*)(smem + OFF_BS);
            int q4 = l >> 2, tc = l & 3;
#pragma unroll
            for (int mt = 0; mt < 2; mt++) {
                int mrow = warp_m * 32 + mt * 16 + q4;
#pragma unroll
                for (int p = 0; p < 4; p++) {
                    int jb = p * 64 + warp_n * 16;
                    if (jb >= nact) continue;
#pragma unroll
                    for (int hn = 0; hn < 2; hn++) {
                        int j = jb + hn * 8 + tc * 2;
                        float b0 = bsp[j], b1 = bsp[j + 1];
                        float* a4 = acc[mt][2 * p + hn];
#pragma unroll
                        for (int half = 0; half < 2; half++) {
                            int m = mrow + half * 8;
                            uint32_t off = (uint32_t)m * XSTR + (uint32_t)j * 2;
                            uint32_t h  = *(uint32_t*)(smem + OFF_XH + off);
                            uint32_t lo = *(uint32_t*)(smem + OFF_XL + off);
                            __nv_bfloat162 H = *(__nv_bfloat162*)&h;
                            __nv_bfloat162 L = *(__nv_bfloat162*)&lo;
                            float c0 = a4[half * 2];
                            float c1 = a4[half * 2 + 1];
                            float x0 = __bfloat162float(H.x) + __bfloat162float(L.x)
                                       + fmaxf(c0 + b0, 0.0f);
                            float x1 = __bfloat162float(H.y) + __bfloat162float(L.y)
                                       + fmaxf(c1 + b1, 0.0f);
                            uint32_t nh, nl;
                            split2(x0, x1, nh, nl);
                            *(uint32_t*)(smem + OFF_XH + off) = nh;
                            *(uint32_t*)(smem + OFF_XL + off) = nl;
                        }
                    }
                }
            }
            __syncthreads();
        } else {
            __syncthreads();
        }
    }

    // ---- final store ----
    {
        int m = t >> 2, q = t & 3;
        float4* dst = (float4*)(out + ((size_t)(m0 + m) * N_ + n) * D_) + q * 16;
        const char* rowH = smem + OFF_XH + m * XSTR;
        const char* rowL = smem + OFF_XL + m * XSTR;
#pragma unroll
        for (int c = 0; c < 16; c++) {
            int k = q * 64 + c * 4;
            uint32_t h0  = *(const uint32_t*)(rowH + k * 2);
            uint32_t l0  = *(const uint32_t*)(rowL + k * 2);
            uint32_t h1  = *(const uint32_t*)(rowH + k * 2 + 4);
            uint32_t l1  = *(const uint32_t*)(rowL + k * 2 + 4);
            __nv_bfloat162 H0 = *(__nv_bfloat162*)&h0, L0 = *(__nv_bfloat162*)&l0;
            __nv_bfloat162 H1 = *(__nv_bfloat162*)&h1, L1 = *(__nv_bfloat162*)&l1;
            float4 v;
            v.x = __bfloat162float(H0.x) + __bfloat162float(L0.x);
            v.y = __bfloat162float(H0.y) + __bfloat162float(L0.y);
            v.z = __bfloat162float(H1.x) + __bfloat162float(L1.x);
            v.w = __bfloat162float(H1.y) + __bfloat162float(L1.y);
            dst[c] = v;
        }
    }
}

// ---------------------------------------------------------------------------
extern "C" void kernel_launch(void* const* d_in, const int* in_sizes, int n_in,
                              void* d_out, int out_size) {
    const float* x  = (const float*)d_in[0];
    const float* w  = (const float*)d_in[1];
    const float* b  = (const float*)d_in[2];
    const float* wm = (const float*)d_in[3];
    const float* bm = (const float*)d_in[4];
    float* out = (float*)d_out;

    prep_w_kernel<<<dim3(N_, 4), 256>>>(w, wm);
    prep_b_kernel<<<N_, D_>>>(b, bm);

    cudaFuncSetAttribute(recur_kernel,
                         cudaFuncAttributeMaxDynamicSharedMemorySize, SMEM_SZ);
    recur_kernel<<<dim3(B_ / MT, N_), NTH, SMEM_SZ>>>(x, out);
}

// round 7
// speedup vs baseline: 1.9698x; 1.0630x over previous
#include <cuda_runtime.h>
#include <cuda_bf16.h>
#include <cstdint>

#define B_ 2048
#define N_ 64
#define D_ 256
#define MT 64
#define NTH 256
#define STEPS 4

// ---------------------------------------------------------------------------
// w image, slab-major: [n][slab(16)][half(hi/lo)][row(256)][16k * bf16 = 32B]
// ---------------------------------------------------------------------------
__device__ uint32_t g_w[(size_t)N_ * 16 * 2 * D_ * 8];   // 16 MB
__device__ float    g_bias[N_ * D_];
__device__ int      g_nact[N_];

__device__ __forceinline__ void split2(float a, float b, uint32_t& hi, uint32_t& lo) {
    __nv_bfloat162 H = __floats2bfloat162_rn(a, b);
    float ra = a - __bfloat162float(H.x);
    float rb = b - __bfloat162float(H.y);
    __nv_bfloat162 L = __floats2bfloat162_rn(ra, rb);
    hi = *reinterpret_cast<uint32_t*>(&H);
    lo = *reinterpret_cast<uint32_t*>(&L);
}

__device__ __forceinline__ uint32_t smem_u32(const void* p) {
    uint32_t a;
    asm("{ .reg .u64 t; cvta.to.shared.u64 t, %1; cvt.u32.u64 %0, t; }"
        : "=r"(a) : "l"(p));
    return a;
}

__device__ __forceinline__ void cp16(uint32_t dst, const void* src) {
    asm volatile("cp.async.ca.shared.global [%0], [%1], 16;"
                 :: "r"(dst), "l"(src) : "memory");
}

#define LDSM4(r, addr) \
    asm volatile("ldmatrix.sync.aligned.m8n8.x4.shared.b16 {%0,%1,%2,%3}, [%4];" \
        : "=r"((r)[0]), "=r"((r)[1]), "=r"((r)[2]), "=r"((r)[3]) : "r"(addr))

#define MMA16816(d, a, b0, b1) \
    asm volatile("mma.sync.aligned.m16n8k16.row.col.f32.bf16.bf16.f32 " \
        "{%0,%1,%2,%3}, {%4,%5,%6,%7}, {%8,%9}, {%0,%1,%2,%3};" \
        : "+f"((d)[0]), "+f"((d)[1]), "+f"((d)[2]), "+f"((d)[3]) \
        : "r"((a)[0]), "r"((a)[1]), "r"((a)[2]), "r"((a)[3]), "r"(b0), "r"(b1))

// ---------------------------------------------------------------------------
// Prep A: split masked w -> slab-major bf16 hi/lo image. grid (64, 16).
// CTA covers 16 j rows; thread (t>>4)=j row, (t&15)=k-slab.
// ---------------------------------------------------------------------------
__global__ void prep_w_kernel(const float* __restrict__ w,
                              const float* __restrict__ wm) {
    int n = blockIdx.x;
    int t = threadIdx.x;
    int j = blockIdx.y * 16 + (t >> 4);
    int c = t & 15;                       // k-slab, k in [c*16, c*16+16)
    const float4* wp = (const float4*)(w  + ((size_t)n * D_ + j) * D_) + c * 4;
    const float4* mp = (const float4*)(wm + ((size_t)n * D_ + j) * D_) + c * 4;
    uint32_t* oH = g_w + ((((size_t)n * 16 + c) * 2 + 0) * D_ + j) * 8;
    uint32_t* oL = g_w + ((((size_t)n * 16 + c) * 2 + 1) * D_ + j) * 8;
#pragma unroll
    for (int i4 = 0; i4 < 4; i4++) {
        float4 a = wp[i4];
        float4 m = mp[i4];
        uint32_t h0, l0, h1, l1;
        split2(a.x * m.x, a.y * m.y, h0, l0);
        split2(a.z * m.z, a.w * m.w, h1, l1);
        oH[i4 * 2] = h0; oH[i4 * 2 + 1] = h1;
        oL[i4 * 2] = l0; oL[i4 * 2 + 1] = l1;
    }
}

__global__ void prep_b_kernel(const float* __restrict__ b,
                              const float* __restrict__ bm) {
    int n = blockIdx.x, t = threadIdx.x;
    __shared__ int cnt;
    if (t == 0) cnt = 0;
    __syncthreads();
    float m = bm[n * D_ + t];
    g_bias[n * D_ + t] = b[n * D_ + t] * m;
    unsigned ballot = __ballot_sync(0xFFFFFFFFu, m != 0.0f);
    if ((t & 31) == 0) atomicAdd(&cnt, __popc(ballot));
    __syncthreads();
    if (t == 0) g_nact[n] = cnt;
}

// ---------------------------------------------------------------------------
// Main. Interleaved warp j-stripes (SMSP balance). B smem image XOR-swizzled
// (16B half h of row j stored at h ^ ((j>>2)&1)) -> conflict-free ldmatrix.
// w slabs streamed with cp.async double buffer (latency hidden by compute).
// ---------------------------------------------------------------------------
#define XSTR    528
#define OFF_XH  0u
#define OFF_XL  33792u
#define OFF_W   67584u
#define WBUF    16384u
#define WHALF   8192u
#define OFF_BS  100352u
#define SMEM_SZ 101376

__global__ __launch_bounds__(NTH, 2)
void recur_kernel(const float* __restrict__ x_in, float* __restrict__ out) {
    extern __shared__ char smem[];
    uint32_t sb = smem_u32(smem);
    int n  = blockIdx.y;
    int m0 = blockIdx.x * MT;
    int t  = threadIdx.x;
    int l  = t & 31;
    int wid = t >> 5;
    int warp_m = wid >> 2;
    int warp_n = wid & 3;

    int nact = g_nact[n];
    ((float*)(smem + OFF_BS))[t] = g_bias[n * D_ + t];

    // ---- initial x load + split ----
    {
        int m = t >> 2, q = t & 3;
        const float4* src =
            (const float4*)(x_in + ((size_t)(m0 + m) * N_ + n) * D_) + q * 16;
        char* rowH = smem + OFF_XH + m * XSTR;
        char* rowL = smem + OFF_XL + m * XSTR;
#pragma unroll
        for (int c = 0; c < 16; c++) {
            float4 v = src[c];
            int k = q * 64 + c * 4;
            uint32_t h0, l0, h1, l1;
            split2(v.x, v.y, h0, l0);
            split2(v.z, v.w, h1, l1);
            *(uint32_t*)(rowH + k * 2)     = h0;
            *(uint32_t*)(rowL + k * 2)     = l0;
            *(uint32_t*)(rowH + k * 2 + 4) = h1;
            *(uint32_t*)(rowL + k * 2 + 4) = l1;
        }
    }

    const int nslab = nact >> 4;
    const int total = STEPS * nslab;
    const bool ldr = (t < nact);
    // gmem base for row t, slab 0, hi half (bytes); slab s adds s*16384, lo +8192
    const char* gw = (const char*)g_w + ((size_t)n * 16 * 2 * D_ + t) * 32;
    // swizzled destination chunk offsets for this row
    const uint32_t swz = ((uint32_t)(t >> 2) & 1u) * 16u;
    const uint32_t c0 = swz, c1 = 16u - swz;

    // preload slab 0 -> buf 0
    if (ldr) {
        uint32_t d = sb + OFF_W + (uint32_t)t * 32;
        cp16(d + c0, gw);
        cp16(d + c1, gw + 16);
        cp16(d + WHALF + c0, gw + 8192);
        cp16(d + WHALF + c1, gw + 8192 + 16);
    }
    asm volatile("cp.async.commit_group;" ::: "memory");
    asm volatile("cp.async.wait_group 0;" ::: "memory");
    __syncthreads();

    const uint32_t aBaseH = sb + OFF_XH + (uint32_t)(warp_m * 32 + (l & 15)) * XSTR
                            + (uint32_t)(l >> 4) * 16;
    const uint32_t aBaseL = aBaseH + (OFF_XL - OFF_XH);
    // B ldmatrix base with XOR swizzle: row r, half hs -> phys half hs^((r>>2)&1)
    const int br = (l & 7) + ((l >> 4) & 1) * 8;
    const int bh = (l >> 3) & 1;
    const uint32_t bBase = sb + OFF_W + (uint32_t)br * 32
                           + (uint32_t)((bh ^ ((br >> 2) & 1)) * 16);

    float acc[2][8][4];

    for (int g = 0; g < total; g++) {
        int buf = g & 1;
        int s = g % nslab;
        if (s == 0) {
#pragma unroll
            for (int i = 0; i < 2; i++)
#pragma unroll
                for (int jn = 0; jn < 8; jn++)
#pragma unroll
                    for (int r = 0; r < 4; r++) acc[i][jn][r] = 0.0f;
        }

        // async prefetch next slab into other buffer
        if (g + 1 < total && ldr) {
            int sn = (g + 1) % nslab;
            const char* srcH = gw + (size_t)sn * 16384;
            uint32_t d = sb + OFF_W + (uint32_t)(buf ^ 1) * WBUF + (uint32_t)t * 32;
            cp16(d + c0, srcH);
            cp16(d + c1, srcH + 16);
            cp16(d + WHALF + c0, srcH + 8192);
            cp16(d + WHALF + c1, srcH + 8192 + 16);
        }
        asm volatile("cp.async.commit_group;" ::: "memory");

        // ---- compute on buffer `buf` (one k16 per slab) ----
        {
            uint32_t aoff = (uint32_t)s * 32;
            uint32_t aH0[4], aH1[4], aL0[4], aL1[4];
            LDSM4(aH0, aBaseH + aoff);
            LDSM4(aH1, aBaseH + 8448 + aoff);
            LDSM4(aL0, aBaseL + aoff);
            LDSM4(aL1, aBaseL + 8448 + aoff);
            const uint32_t wOff = (uint32_t)buf * WBUF;
#pragma unroll
            for (int p = 0; p < 4; p++) {
                int n0 = p * 64 + warp_n * 16;   // interleaved stripe
                if (n0 < nact) {
                    uint32_t bH[4], bL[4];
                    uint32_t boff = wOff + (uint32_t)n0 * 32;
                    LDSM4(bH, bBase + boff);
                    LDSM4(bL, bBase + boff + WHALF);
                    MMA16816(acc[0][2 * p],     aH0, bH[0], bH[1]);
                    MMA16816(acc[0][2 * p + 1], aH0, bH[2], bH[3]);
                    MMA16816(acc[1][2 * p],     aH1, bH[0], bH[1]);
                    MMA16816(acc[1][2 * p + 1], aH1, bH[2], bH[3]);
                    MMA16816(acc[0][2 * p],     aL0, bH[0], bH[1]);
                    MMA16816(acc[0][2 * p + 1], aL0, bH[2], bH[3]);
                    MMA16816(acc[1][2 * p],     aL1, bH[0], bH[1]);
                    MMA16816(acc[1][2 * p + 1], aL1, bH[2], bH[3]);
                    MMA16816(acc[0][2 * p],     aH0, bL[0], bL[1]);
                    MMA16816(acc[0][2 * p + 1], aH0, bL[2], bL[3]);
                    MMA16816(acc[1][2 * p],     aH1, bL[0], bL[1]);
                    MMA16816(acc[1][2 * p + 1], aH1, bL[2], bL[3]);
                }
            }
        }

        if (s == nslab - 1) {
            __syncthreads();
            // ---- epilogue: x += relu(acc + b) over this warp's stripes ----
            const float* bsp = (const float*)(smem + OFF_BS);
            int q4 = l >> 2, tc = l & 3;
#pragma unroll
            for (int mt = 0; mt < 2; mt++) {
                int mrow = warp_m * 32 + mt * 16 + q4;
#pragma unroll
                for (int p = 0; p < 4; p++) {
                    int jb = p * 64 + warp_n * 16;
                    if (jb >= nact) continue;
#pragma unroll
                    for (int hn = 0; hn < 2; hn++) {
                        int j = jb + hn * 8 + tc * 2;
                        float b0 = bsp[j], b1 = bsp[j + 1];
                        float* a4 = acc[mt][2 * p + hn];
#pragma unroll
                        for (int half = 0; half < 2; half++) {
                            int m = mrow + half * 8;
                            uint32_t off = (uint32_t)m * XSTR + (uint32_t)j * 2;
                            uint32_t h  = *(uint32_t*)(smem + OFF_XH + off);
                            uint32_t lo = *(uint32_t*)(smem + OFF_XL + off);
                            __nv_bfloat162 H = *(__nv_bfloat162*)&h;
                            __nv_bfloat162 L = *(__nv_bfloat162*)&lo;
                            float cc0 = a4[half * 2];
                            float cc1 = a4[half * 2 + 1];
                            float x0 = __bfloat162float(H.x) + __bfloat162float(L.x)
                                       + fmaxf(cc0 + b0, 0.0f);
                            float x1 = __bfloat162float(H.y) + __bfloat162float(L.y)
                                       + fmaxf(cc1 + b1, 0.0f);
                            uint32_t nh, nl;
                            split2(x0, x1, nh, nl);
                            *(uint32_t*)(smem + OFF_XH + off) = nh;
                            *(uint32_t*)(smem + OFF_XL + off) = nl;
                        }
                    }
                }
            }
            asm volatile("cp.async.wait_group 0;" ::: "memory");
            __syncthreads();
        } else {
            asm volatile("cp.async.wait_group 0;" ::: "memory");
            __syncthreads();
        }
    }

    // ---- final store ----
    {
        int m = t >> 2, q = t & 3;
        float4* dst = (float4*)(out + ((size_t)(m0 + m) * N_ + n) * D_) + q * 16;
        const char* rowH = smem + OFF_XH + m * XSTR;
        const char* rowL = smem + OFF_XL + m * XSTR;
#pragma unroll
        for (int c = 0; c < 16; c++) {
            int k = q * 64 + c * 4;
            uint32_t h0  = *(const uint32_t*)(rowH + k * 2);
            uint32_t l0  = *(const uint32_t*)(rowL + k * 2);
            uint32_t h1  = *(const uint32_t*)(rowH + k * 2 + 4);
            uint32_t l1  = *(const uint32_t*)(rowL + k * 2 + 4);
            __nv_bfloat162 H0 = *(__nv_bfloat162*)&h0, L0 = *(__nv_bfloat162*)&l0;
            __nv_bfloat162 H1 = *(__nv_bfloat162*)&h1, L1 = *(__nv_bfloat162*)&l1;
            float4 v;
            v.x = __bfloat162float(H0.x) + __bfloat162float(L0.x);
            v.y = __bfloat162float(H0.y) + __bfloat162float(L0.y);
            v.z = __bfloat162float(H1.x) + __bfloat162float(L1.x);
            v.w = __bfloat162float(H1.y) + __bfloat162float(L1.y);
            dst[c] = v;
        }
    }
}

// ---------------------------------------------------------------------------
extern "C" void kernel_launch(void* const* d_in, const int* in_sizes, int n_in,
                              void* d_out, int out_size) {
    const float* x  = (const float*)d_in[0];
    const float* w  = (const float*)d_in[1];
    const float* b  = (const float*)d_in[2];
    const float* wm = (const float*)d_in[3];
    const float* bm = (const float*)d_in[4];
    float* out = (float*)d_out;

    prep_w_kernel<<<dim3(N_, 16), 256>>>(w, wm);
    prep_b_kernel<<<N_, D_>>>(b, bm);

    cudaFuncSetAttribute(recur_kernel,
                         cudaFuncAttributeMaxDynamicSharedMemorySize, SMEM_SZ);
    recur_kernel<<<dim3(B_ / MT, N_), NTH, SMEM_SZ>>>(x, out);
}

// round 8
// speedup vs baseline: 2.6831x; 1.3621x over previous
#include <cuda_runtime.h>
#include <cuda_fp16.h>
#include <cstdint>

#define B_ 2048
#define N_ 64
#define D_ 256
#define MT 64
#define NTH 256
#define STEPS 4

// ---------------------------------------------------------------------------
// w image (fp16, masked), slab-major: [n][slab16(16)][row(256)][16k*fp16=32B]
// ---------------------------------------------------------------------------
__device__ uint32_t g_w[(size_t)N_ * 16 * D_ * 8];   // 8 MB
__device__ float    g_bias[N_ * D_];
__device__ int      g_nact[N_];

// split pair of fp32 into packed fp16x2 hi + fp16x2 lo (residual)
__device__ __forceinline__ void split2h(float a, float b, uint32_t& hi, uint32_t& lo) {
    __half2 H = __floats2half2_rn(a, b);
    float ra = a - __half2float(H.x);
    float rb = b - __half2float(H.y);
    __half2 L = __floats2half2_rn(ra, rb);
    hi = *reinterpret_cast<uint32_t*>(&H);
    lo = *reinterpret_cast<uint32_t*>(&L);
}

__device__ __forceinline__ uint32_t smem_u32(const void* p) {
    uint32_t a;
    asm("{ .reg .u64 t; cvta.to.shared.u64 t, %1; cvt.u32.u64 %0, t; }"
        : "=r"(a) : "l"(p));
    return a;
}

__device__ __forceinline__ void cp16(uint32_t dst, const void* src) {
    asm volatile("cp.async.ca.shared.global [%0], [%1], 16;"
                 :: "r"(dst), "l"(src) : "memory");
}

#define LDSM4(r, addr) \
    asm volatile("ldmatrix.sync.aligned.m8n8.x4.shared.b16 {%0,%1,%2,%3}, [%4];" \
        : "=r"((r)[0]), "=r"((r)[1]), "=r"((r)[2]), "=r"((r)[3]) : "r"(addr))

#define MMA16816(d, a, b0, b1) \
    asm volatile("mma.sync.aligned.m16n8k16.row.col.f32.f16.f16.f32 " \
        "{%0,%1,%2,%3}, {%4,%5,%6,%7}, {%8,%9}, {%0,%1,%2,%3};" \
        : "+f"((d)[0]), "+f"((d)[1]), "+f"((d)[2]), "+f"((d)[3]) \
        : "r"((a)[0]), "r"((a)[1]), "r"((a)[2]), "r"((a)[3]), "r"(b0), "r"(b1))

// ---------------------------------------------------------------------------
// Prep A: masked w -> fp16 slab-major image. grid (64, 16), block 256.
// thread: j = by*16 + (t>>4), slab c = t&15.
// ---------------------------------------------------------------------------
__global__ void prep_w_kernel(const float* __restrict__ w,
                              const float* __restrict__ wm) {
    int n = blockIdx.x;
    int t = threadIdx.x;
    int j = blockIdx.y * 16 + (t >> 4);
    int c = t & 15;
    const float4* wp = (const float4*)(w  + ((size_t)n * D_ + j) * D_) + c * 4;
    const float4* mp = (const float4*)(wm + ((size_t)n * D_ + j) * D_) + c * 4;
    uint32_t* o = g_w + (((size_t)n * 16 + c) * D_ + j) * 8;
#pragma unroll
    for (int i4 = 0; i4 < 4; i4++) {
        float4 a = wp[i4];
        float4 m = mp[i4];
        __half2 h0 = __floats2half2_rn(a.x * m.x, a.y * m.y);
        __half2 h1 = __floats2half2_rn(a.z * m.z, a.w * m.w);
        o[i4 * 2]     = *reinterpret_cast<uint32_t*>(&h0);
        o[i4 * 2 + 1] = *reinterpret_cast<uint32_t*>(&h1);
    }
}

__global__ void prep_b_kernel(const float* __restrict__ b,
                              const float* __restrict__ bm) {
    int n = blockIdx.x, t = threadIdx.x;
    __shared__ int cnt;
    if (t == 0) cnt = 0;
    __syncthreads();
    float m = bm[n * D_ + t];
    g_bias[n * D_ + t] = b[n * D_ + t] * m;
    unsigned ballot = __ballot_sync(0xFFFFFFFFu, m != 0.0f);
    if ((t & 31) == 0) atomicAdd(&cnt, __popc(ballot));
    __syncthreads();
    if (t == 0) g_nact[n] = cnt;
}

// ---------------------------------------------------------------------------
// Main. 2-term fp16 split (xh*w + xl*w), interleaved warp j-stripes, B smem
// XOR-swizzled, cp.async double-buffered slabs of k=32 (two k16 sub-slabs).
// ---------------------------------------------------------------------------
#define XSTR    528
#define OFF_XH  0u
#define OFF_XL  33792u
#define OFF_W   67584u          // [buf(2)][k16(2)][256 rows * 32B] = 2*16384
#define WBUF    16384u
#define WSUB    8192u
#define OFF_BS  100352u
#define SMEM_SZ 101376

__global__ __launch_bounds__(NTH, 2)
void recur_kernel(const float* __restrict__ x_in, float* __restrict__ out) {
    extern __shared__ char smem[];
    uint32_t sb = smem_u32(smem);
    int n  = blockIdx.y;
    int m0 = blockIdx.x * MT;
    int t  = threadIdx.x;
    int l  = t & 31;
    int wid = t >> 5;
    int warp_m = wid >> 2;
    int warp_n = wid & 3;

    int nact = g_nact[n];
    ((float*)(smem + OFF_BS))[t] = g_bias[n * D_ + t];

    // ---- initial x load + fp16 split ----
    {
        int m = t >> 2, q = t & 3;
        const float4* src =
            (const float4*)(x_in + ((size_t)(m0 + m) * N_ + n) * D_) + q * 16;
        char* rowH = smem + OFF_XH + m * XSTR;
        char* rowL = smem + OFF_XL + m * XSTR;
#pragma unroll
        for (int c = 0; c < 16; c++) {
            float4 v = src[c];
            int k = q * 64 + c * 4;
            uint32_t h0, l0, h1, l1;
            split2h(v.x, v.y, h0, l0);
            split2h(v.z, v.w, h1, l1);
            *(uint32_t*)(rowH + k * 2)     = h0;
            *(uint32_t*)(rowL + k * 2)     = l0;
            *(uint32_t*)(rowH + k * 2 + 4) = h1;
            *(uint32_t*)(rowL + k * 2 + 4) = l1;
        }
    }

    const int nslab = nact >> 5;           // k-slabs of 32
    const int total = STEPS * nslab;
    const bool ldr = (t < nact);
    // gmem base for row t, sub-slab 0 (bytes); sub-slab u adds u*8192
    const char* gw = (const char*)g_w + ((size_t)n * 16 * D_ + t) * 32;
    const uint32_t swz = ((uint32_t)(t >> 2) & 1u) * 16u;
    const uint32_t c0 = swz, c1 = 16u - swz;

    // preload slab 0 -> buf 0 (sub-slabs 0,1)
    if (ldr) {
        uint32_t d = sb + OFF_W + (uint32_t)t * 32;
        cp16(d + c0, gw);
        cp16(d + c1, gw + 16);
        cp16(d + WSUB + c0, gw + 8192);
        cp16(d + WSUB + c1, gw + 8192 + 16);
    }
    asm volatile("cp.async.commit_group;" ::: "memory");
    asm volatile("cp.async.wait_group 0;" ::: "memory");
    __syncthreads();

    const uint32_t aBaseH = sb + OFF_XH + (uint32_t)(warp_m * 32 + (l & 15)) * XSTR
                            + (uint32_t)(l >> 4) * 16;
    const uint32_t aBaseL = aBaseH + (OFF_XL - OFF_XH);
    const int br = (l & 7) + ((l >> 4) & 1) * 8;
    const int bh = (l >> 3) & 1;
    const uint32_t bBase = sb + OFF_W + (uint32_t)br * 32
                           + (uint32_t)((bh ^ ((br >> 2) & 1)) * 16);

    float acc[2][8][4];

    for (int g = 0; g < total; g++) {
        int buf = g & 1;
        int s = g % nslab;
        if (s == 0) {
#pragma unroll
            for (int i = 0; i < 2; i++)
#pragma unroll
                for (int jn = 0; jn < 8; jn++)
#pragma unroll
                    for (int r = 0; r < 4; r++) acc[i][jn][r] = 0.0f;
        }

        // async prefetch next k32 slab into other buffer
        if (g + 1 < total && ldr) {
            int sn = (g + 1) % nslab;
            const char* src = gw + (size_t)sn * 16384;
            uint32_t d = sb + OFF_W + (uint32_t)(buf ^ 1) * WBUF + (uint32_t)t * 32;
            cp16(d + c0, src);
            cp16(d + c1, src + 16);
            cp16(d + WSUB + c0, src + 8192);
            cp16(d + WSUB + c1, src + 8192 + 16);
        }
        asm volatile("cp.async.commit_group;" ::: "memory");

        // ---- compute on buffer `buf`: two k16 sub-slabs ----
        const uint32_t wOff = (uint32_t)buf * WBUF;
#pragma unroll
        for (int kk = 0; kk < 2; kk++) {
            uint32_t aoff = (uint32_t)(s * 64 + kk * 32);
            uint32_t aH0[4], aH1[4], aL0[4], aL1[4];
            LDSM4(aH0, aBaseH + aoff);
            LDSM4(aH1, aBaseH + 8448 + aoff);
            LDSM4(aL0, aBaseL + aoff);
            LDSM4(aL1, aBaseL + 8448 + aoff);
            uint32_t kOff = wOff + (uint32_t)kk * WSUB;
#pragma unroll
            for (int p = 0; p < 4; p++) {
                int n0 = p * 64 + warp_n * 16;   // interleaved stripe
                if (n0 < nact) {
                    uint32_t bW[4];
                    LDSM4(bW, bBase + kOff + (uint32_t)n0 * 32);
                    MMA16816(acc[0][2 * p],     aH0, bW[0], bW[1]);
                    MMA16816(acc[0][2 * p + 1], aH0, bW[2], bW[3]);
                    MMA16816(acc[1][2 * p],     aH1, bW[0], bW[1]);
                    MMA16816(acc[1][2 * p + 1], aH1, bW[2], bW[3]);
                    MMA16816(acc[0][2 * p],     aL0, bW[0], bW[1]);
                    MMA16816(acc[0][2 * p + 1], aL0, bW[2], bW[3]);
                    MMA16816(acc[1][2 * p],     aL1, bW[0], bW[1]);
                    MMA16816(acc[1][2 * p + 1], aL1, bW[2], bW[3]);
                }
            }
        }

        if (s == nslab - 1) {
            __syncthreads();
            // ---- epilogue: x += relu(acc + b), re-split fp16 ----
            const float* bsp = (const float*)(smem + OFF_BS);
            int q4 = l >> 2, tc = l & 3;
#pragma unroll
            for (int mt = 0; mt < 2; mt++) {
                int mrow = warp_m * 32 + mt * 16 + q4;
#pragma unroll
                for (int p = 0; p < 4; p++) {
                    int jb = p * 64 + warp_n * 16;
                    if (jb >= nact) continue;
#pragma unroll
                    for (int hn = 0; hn < 2; hn++) {
                        int j = jb + hn * 8 + tc * 2;
                        float b0 = bsp[j], b1 = bsp[j + 1];
                        float* a4 = acc[mt][2 * p + hn];
#pragma unroll
                        for (int half = 0; half < 2; half++) {
                            int m = mrow + half * 8;
                            uint32_t off = (uint32_t)m * XSTR + (uint32_t)j * 2;
                            uint32_t h  = *(uint32_t*)(smem + OFF_XH + off);
                            uint32_t lo = *(uint32_t*)(smem + OFF_XL + off);
                            __half2 H = *(__half2*)&h;
                            __half2 L = *(__half2*)&lo;
                            float cc0 = a4[half * 2];
                            float cc1 = a4[half * 2 + 1];
                            float x0 = __half2float(H.x) + __half2float(L.x)
                                       + fmaxf(cc0 + b0, 0.0f);
                            float x1 = __half2float(H.y) + __half2float(L.y)
                                       + fmaxf(cc1 + b1, 0.0f);
                            uint32_t nh, nl;
                            split2h(x0, x1, nh, nl);
                            *(uint32_t*)(smem + OFF_XH + off) = nh;
                            *(uint32_t*)(smem + OFF_XL + off) = nl;
                        }
                    }
                }
            }
            asm volatile("cp.async.wait_group 0;" ::: "memory");
            __syncthreads();
        } else {
            asm volatile("cp.async.wait_group 0;" ::: "memory");
            __syncthreads();
        }
    }

    // ---- final store: x = hi + lo ----
    {
        int m = t >> 2, q = t & 3;
        float4* dst = (float4*)(out + ((size_t)(m0 + m) * N_ + n) * D_) + q * 16;
        const char* rowH = smem + OFF_XH + m * XSTR;
        const char* rowL = smem + OFF_XL + m * XSTR;
#pragma unroll
        for (int c = 0; c < 16; c++) {
            int k = q * 64 + c * 4;
            uint32_t h0  = *(const uint32_t*)(rowH + k * 2);
            uint32_t l0  = *(const uint32_t*)(rowL + k * 2);
            uint32_t h1  = *(const uint32_t*)(rowH + k * 2 + 4);
            uint32_t l1  = *(const uint32_t*)(rowL + k * 2 + 4);
            __half2 H0 = *(__half2*)&h0, L0 = *(__half2*)&l0;
            __half2 H1 = *(__half2*)&h1, L1 = *(__half2*)&l1;
            float4 v;
            v.x = __half2float(H0.x) + __half2float(L0.x);
            v.y = __half2float(H0.y) + __half2float(L0.y);
            v.z = __half2float(H1.x) + __half2float(L1.x);
            v.w = __half2float(H1.y) + __half2float(L1.y);
            dst[c] = v;
        }
    }
}

// ---------------------------------------------------------------------------
extern "C" void kernel_launch(void* const* d_in, const int* in_sizes, int n_in,
                              void* d_out, int out_size) {
    const float* x  = (const float*)d_in[0];
    const float* w  = (const float*)d_in[1];
    const float* b  = (const float*)d_in[2];
    const float* wm = (const float*)d_in[3];
    const float* bm = (const float*)d_in[4];
    float* out = (float*)d_out;

    prep_w_kernel<<<dim3(N_, 16), 256>>>(w, wm);
    prep_b_kernel<<<N_, D_>>>(b, bm);

    cudaFuncSetAttribute(recur_kernel,
                         cudaFuncAttributeMaxDynamicSharedMemorySize, SMEM_SZ);
    recur_kernel<<<dim3(B_ / MT, N_), NTH, SMEM_SZ>>>(x, out);
}

// round 9
// speedup vs baseline: 3.0526x; 1.1377x over previous
#include <cuda_runtime.h>
#include <cuda_fp16.h>
#include <cstdint>

#define B_ 2048
#define N_ 64
#define D_ 256
#define MT 64
#define NTH 256
#define STEPS 4

// ---------------------------------------------------------------------------
// w image (fp16, masked), slab-major: [n][slab16(16)][row(256)][16k*fp16=32B]
// ---------------------------------------------------------------------------
__device__ uint32_t g_w[(size_t)N_ * 16 * D_ * 8];   // 8 MB
__device__ float    g_bias[N_ * D_];
__device__ int      g_nact[N_];

__device__ __forceinline__ void split2h(float a, float b, uint32_t& hi, uint32_t& lo) {
    __half2 H = __floats2half2_rn(a, b);
    float ra = a - __half2float(H.x);
    float rb = b - __half2float(H.y);
    __half2 L = __floats2half2_rn(ra, rb);
    hi = *reinterpret_cast<uint32_t*>(&H);
    lo = *reinterpret_cast<uint32_t*>(&L);
}

__device__ __forceinline__ uint32_t smem_u32(const void* p) {
    uint32_t a;
    asm("{ .reg .u64 t; cvta.to.shared.u64 t, %1; cvt.u32.u64 %0, t; }"
        : "=r"(a) : "l"(p));
    return a;
}

__device__ __forceinline__ void cp16(uint32_t dst, const void* src) {
    asm volatile("cp.async.ca.shared.global [%0], [%1], 16;"
                 :: "r"(dst), "l"(src) : "memory");
}

#define LDSM4(r, addr) \
    asm volatile("ldmatrix.sync.aligned.m8n8.x4.shared.b16 {%0,%1,%2,%3}, [%4];" \
        : "=r"((r)[0]), "=r"((r)[1]), "=r"((r)[2]), "=r"((r)[3]) : "r"(addr))

#define MMA16816(d, a, b0, b1) \
    asm volatile("mma.sync.aligned.m16n8k16.row.col.f32.f16.f16.f32 " \
        "{%0,%1,%2,%3}, {%4,%5,%6,%7}, {%8,%9}, {%0,%1,%2,%3};" \
        : "+f"((d)[0]), "+f"((d)[1]), "+f"((d)[2]), "+f"((d)[3]) \
        : "r"((a)[0]), "r"((a)[1]), "r"((a)[2]), "r"((a)[3]), "r"(b0), "r"(b1))

// ---------------------------------------------------------------------------
// Fused prep: masked fp16 w image; block.y==0 also does bias + nact.
// ---------------------------------------------------------------------------
__global__ void prep_kernel(const float* __restrict__ w,
                            const float* __restrict__ wm,
                            const float* __restrict__ b,
                            const float* __restrict__ bm) {
    int n = blockIdx.x;
    int t = threadIdx.x;
    int j = blockIdx.y * 16 + (t >> 4);
    int c = t & 15;
    const float4* wp = (const float4*)(w  + ((size_t)n * D_ + j) * D_) + c * 4;
    const float4* mp = (const float4*)(wm + ((size_t)n * D_ + j) * D_) + c * 4;
    uint32_t* o = g_w + (((size_t)n * 16 + c) * D_ + j) * 8;
#pragma unroll
    for (int i4 = 0; i4 < 4; i4++) {
        float4 a = wp[i4];
        float4 m = mp[i4];
        __half2 h0 = __floats2half2_rn(a.x * m.x, a.y * m.y);
        __half2 h1 = __floats2half2_rn(a.z * m.z, a.w * m.w);
        o[i4 * 2]     = *reinterpret_cast<uint32_t*>(&h0);
        o[i4 * 2 + 1] = *reinterpret_cast<uint32_t*>(&h1);
    }
    if (blockIdx.y == 0) {
        __shared__ int cnt;
        if (t == 0) cnt = 0;
        __syncthreads();
        float m = bm[n * D_ + t];
        g_bias[n * D_ + t] = b[n * D_ + t] * m;
        unsigned ballot = __ballot_sync(0xFFFFFFFFu, m != 0.0f);
        if ((t & 31) == 0) atomicAdd(&cnt, __popc(ballot));
        __syncthreads();
        if (t == 0) g_nact[n] = cnt;
    }
}

// ---------------------------------------------------------------------------
#define XSTR    528
#define OFF_XH  0u
#define OFF_XL  33792u
#define OFF_W   67584u
#define WBUF    16384u
#define WSUB    8192u
#define OFF_BS  100352u
#define SMEM_SZ 101376

// Templated mainloop: NACT compile-time -> static slab unroll, static guards.
template<int NACT>
__device__ __forceinline__ void run_main(
    char* smem, const char* gw, bool ldr, uint32_t wdst,
    uint32_t c0, uint32_t c1, uint32_t aBaseH, uint32_t aBaseL,
    uint32_t bBase, int warp_m, int warp_n, int l)
{
    constexpr int NSLAB = NACT >> 5;
    const int tc = l & 3;

    // bias cache (step-invariant): 16 regs
    const float* bsp = (const float*)(smem + OFF_BS);
    float bias_r[4][2][2];
#pragma unroll
    for (int p = 0; p < 4; p++) {
        if (NACT == 256 || p * 64 + warp_n * 16 < NACT) {
#pragma unroll
            for (int hn = 0; hn < 2; hn++) {
                int j = p * 64 + warp_n * 16 + hn * 8 + tc * 2;
                bias_r[p][hn][0] = bsp[j];
                bias_r[p][hn][1] = bsp[j + 1];
            }
        }
    }

    float acc[2][8][4];
    uint32_t buf = 0;

    for (int step = 0; step < STEPS; step++) {
#pragma unroll
        for (int i = 0; i < 2; i++)
#pragma unroll
            for (int jn = 0; jn < 8; jn++)
#pragma unroll
                for (int r = 0; r < 4; r++) acc[i][jn][r] = 0.0f;

#pragma unroll
        for (int s = 0; s < NSLAB; s++) {
            // async prefetch next slab (slab 0 of next step when wrapping)
            bool last = (step == STEPS - 1) && (s == NSLAB - 1);
            if (!last && ldr) {
                int sn = (s + 1 == NSLAB) ? 0 : s + 1;
                const char* src = gw + (size_t)sn * 16384;
                uint32_t d = wdst + (buf ^ 1u) * WBUF;
                cp16(d + c0, src);
                cp16(d + c1, src + 16);
                cp16(d + WSUB + c0, src + 8192);
                cp16(d + WSUB + c1, src + 8192 + 16);
            }
            asm volatile("cp.async.commit_group;" ::: "memory");

            // ---- compute: two k16 sub-slabs ----
            const uint32_t wOff = buf * WBUF;
#pragma unroll
            for (int kk = 0; kk < 2; kk++) {
                const uint32_t aoff = (uint32_t)(s * 64 + kk * 32);
                uint32_t aH0[4], aH1[4], aL0[4], aL1[4];
                LDSM4(aH0, aBaseH + aoff);
                LDSM4(aH1, aBaseH + 8448 + aoff);
                LDSM4(aL0, aBaseL + aoff);
                LDSM4(aL1, aBaseL + 8448 + aoff);
                const uint32_t kOff = wOff + (uint32_t)kk * WSUB;
#pragma unroll
                for (int p = 0; p < 4; p++) {
                    if (NACT == 256 || p * 64 + warp_n * 16 < NACT) {
                        uint32_t bW[4];
                        LDSM4(bW, bBase + kOff + (uint32_t)(p * 64 + warp_n * 16) * 32);
                        MMA16816(acc[0][2 * p],     aH0, bW[0], bW[1]);
                        MMA16816(acc[0][2 * p + 1], aH0, bW[2], bW[3]);
                        MMA16816(acc[1][2 * p],     aH1, bW[0], bW[1]);
                        MMA16816(acc[1][2 * p + 1], aH1, bW[2], bW[3]);
                        MMA16816(acc[0][2 * p],     aL0, bW[0], bW[1]);
                        MMA16816(acc[0][2 * p + 1], aL0, bW[2], bW[3]);
                        MMA16816(acc[1][2 * p],     aL1, bW[0], bW[1]);
                        MMA16816(acc[1][2 * p + 1], aL1, bW[2], bW[3]);
                    }
                }
            }

            if (s < NSLAB - 1) {
                asm volatile("cp.async.wait_group 0;" ::: "memory");
                __syncthreads();
            }
            buf ^= 1u;
        }

        // ---- epilogue: x += relu(acc + b), re-split fp16 ----
        __syncthreads();
        int q4 = l >> 2;
#pragma unroll
        for (int mt = 0; mt < 2; mt++) {
            int mrow = warp_m * 32 + mt * 16 + q4;
#pragma unroll
            for (int p = 0; p < 4; p++) {
                if (!(NACT == 256 || p * 64 + warp_n * 16 < NACT)) continue;
#pragma unroll
                for (int hn = 0; hn < 2; hn++) {
                    int j = p * 64 + warp_n * 16 + hn * 8 + tc * 2;
                    float b0 = bias_r[p][hn][0], b1 = bias_r[p][hn][1];
                    float* a4 = acc[mt][2 * p + hn];
#pragma unroll
                    for (int half = 0; half < 2; half++) {
                        int m = mrow + half * 8;
                        uint32_t off = (uint32_t)m * XSTR + (uint32_t)j * 2;
                        uint32_t h  = *(uint32_t*)(smem + OFF_XH + off);
                        uint32_t lo = *(uint32_t*)(smem + OFF_XL + off);
                        __half2 H = *(__half2*)&h;
                        __half2 L = *(__half2*)&lo;
                        float x0 = __half2float(H.x) + __half2float(L.x)
                                   + fmaxf(a4[half * 2]     + b0, 0.0f);
                        float x1 = __half2float(H.y) + __half2float(L.y)
                                   + fmaxf(a4[half * 2 + 1] + b1, 0.0f);
                        uint32_t nh, nl;
                        split2h(x0, x1, nh, nl);
                        *(uint32_t*)(smem + OFF_XH + off) = nh;
                        *(uint32_t*)(smem + OFF_XL + off) = nl;
                    }
                }
            }
        }
        asm volatile("cp.async.wait_group 0;" ::: "memory");
        __syncthreads();
    }
}

__global__ __launch_bounds__(NTH, 2)
void recur_kernel(const float* __restrict__ x_in, float* __restrict__ out) {
    extern __shared__ char smem[];
    uint32_t sb = smem_u32(smem);
    int n  = blockIdx.y;
    int m0 = blockIdx.x * MT;
    int t  = threadIdx.x;
    int l  = t & 31;
    int wid = t >> 5;
    int warp_m = wid >> 2;
    int warp_n = wid & 3;

    int nact = g_nact[n];
    ((float*)(smem + OFF_BS))[t] = g_bias[n * D_ + t];

    // ---- initial x load + fp16 split ----
    {
        int m = t >> 2, q = t & 3;
        const float4* src =
            (const float4*)(x_in + ((size_t)(m0 + m) * N_ + n) * D_) + q * 16;
        char* rowH = smem + OFF_XH + m * XSTR;
        char* rowL = smem + OFF_XL + m * XSTR;
#pragma unroll
        for (int c = 0; c < 16; c++) {
            float4 v = src[c];
            int k = q * 64 + c * 4;
            uint32_t h0, l0, h1, l1;
            split2h(v.x, v.y, h0, l0);
            split2h(v.z, v.w, h1, l1);
            *(uint32_t*)(rowH + k * 2)     = h0;
            *(uint32_t*)(rowL + k * 2)     = l0;
            *(uint32_t*)(rowH + k * 2 + 4) = h1;
            *(uint32_t*)(rowL + k * 2 + 4) = l1;
        }
    }

    const bool ldr = (t < nact);
    const char* gw = (const char*)g_w + ((size_t)n * 16 * D_ + t) * 32;
    const uint32_t swz = ((uint32_t)(t >> 2) & 1u) * 16u;
    const uint32_t c0 = swz, c1 = 16u - swz;
    const uint32_t wdst = sb + OFF_W + (uint32_t)t * 32;

    // preload slab 0 -> buf 0
    if (ldr) {
        cp16(wdst + c0, gw);
        cp16(wdst + c1, gw + 16);
        cp16(wdst + WSUB + c0, gw + 8192);
        cp16(wdst + WSUB + c1, gw + 8192 + 16);
    }
    asm volatile("cp.async.commit_group;" ::: "memory");
    asm volatile("cp.async.wait_group 0;" ::: "memory");
    __syncthreads();

    const uint32_t aBaseH = sb + OFF_XH + (uint32_t)(warp_m * 32 + (l & 15)) * XSTR
                            + (uint32_t)(l >> 4) * 16;
    const uint32_t aBaseL = aBaseH + (OFF_XL - OFF_XH);
    const int br = (l & 7) + ((l >> 4) & 1) * 8;
    const int bh = (l >> 3) & 1;
    const uint32_t bBase = sb + OFF_W + (uint32_t)br * 32
                           + (uint32_t)((bh ^ ((br >> 2) & 1)) * 16);

    switch (nact) {
        case 128: run_main<128>(smem, gw, ldr, wdst, c0, c1, aBaseH, aBaseL, bBase, warp_m, warp_n, l); break;
        case 160: run_main<160>(smem, gw, ldr, wdst, c0, c1, aBaseH, aBaseL, bBase, warp_m, warp_n, l); break;
        case 192: run_main<192>(smem, gw, ldr, wdst, c0, c1, aBaseH, aBaseL, bBase, warp_m, warp_n, l); break;
        case 224: run_main<224>(smem, gw, ldr, wdst, c0, c1, aBaseH, aBaseL, bBase, warp_m, warp_n, l); break;
        default:  run_main<256>(smem, gw, ldr, wdst, c0, c1, aBaseH, aBaseL, bBase, warp_m, warp_n, l); break;
    }

    // ---- final store: x = hi + lo ----
    {
        int m = t >> 2, q = t & 3;
        float4* dst = (float4*)(out + ((size_t)(m0 + m) * N_ + n) * D_) + q * 16;
        const char* rowH = smem + OFF_XH + m * XSTR;
        const char* rowL = smem + OFF_XL + m * XSTR;
#pragma unroll
        for (int c = 0; c < 16; c++) {
            int k = q * 64 + c * 4;
            uint32_t h0  = *(const uint32_t*)(rowH + k * 2);
            uint32_t l0  = *(const uint32_t*)(rowL + k * 2);
            uint32_t h1  = *(const uint32_t*)(rowH + k * 2 + 4);
            uint32_t l1  = *(const uint32_t*)(rowL + k * 2 + 4);
            __half2 H0 = *(__half2*)&h0, L0 = *(__half2*)&l0;
            __half2 H1 = *(__half2*)&h1, L1 = *(__half2*)&l1;
            float4 v;
            v.x = __half2float(H0.x) + __half2float(L0.x);
            v.y = __half2float(H0.y) + __half2float(L0.y);
            v.z = __half2float(H1.x) + __half2float(L1.x);
            v.w = __half2float(H1.y) + __half2float(L1.y);
            dst[c] = v;
        }
    }
}

// ---------------------------------------------------------------------------
extern "C" void kernel_launch(void* const* d_in, const int* in_sizes, int n_in,
                              void* d_out, int out_size) {
    const float* x  = (const float*)d_in[0];
    const float* w  = (const float*)d_in[1];
    const float* b  = (const float*)d_in[2];
    const float* wm = (const float*)d_in[3];
    const float* bm = (const float*)d_in[4];
    float* out = (float*)d_out;

    prep_kernel<<<dim3(N_, 16), 256>>>(w, wm, b, bm);

    cudaFuncSetAttribute(recur_kernel,
                         cudaFuncAttributeMaxDynamicSharedMemorySize, SMEM_SZ);
    recur_kernel<<<dim3(B_ / MT, N_), NTH, SMEM_SZ>>>(x, out);
}